// round 4
// baseline (speedup 1.0000x reference)
#include <cuda_runtime.h>
#include <math.h>
#include <stdint.h>

#define T_TOKENS 16384
#define DDIM     2048
#define NEXP     256
#define TOPK     8
#define BM       128
#define BN       128
#define BK       16
#define NKT      (DDIM / BK)            // 128 k-tiles

#define A_STAGE  (BM * BK * 2)          // 4096 floats (hi+lo interleaved in frag order)
#define B_STAGE  (BN * BK * 2)          // 4096 floats
#define STAGE    (A_STAGE + B_STAGE)    // 8192 floats
#define SMEM_BYTES (2 * STAGE * 4)      // 65536 B

// logits scratch (device global: allocation-free)
__device__ float g_logits[(size_t)T_TOKENS * NEXP];

// Split fp32 x into exact tf32 pair (hi, lo): x = hi + lo + eps, |eps| ~ 2^-22|x|.
// All four cross-products hi/lo x hi/lo are EXACT tf32 x tf32 products.
static __device__ __forceinline__ uint2 split_tf32(float x) {
    uint32_t h, l;
    asm("cvt.rna.tf32.f32 %0, %1;" : "=r"(h) : "f"(x));
    float r = x - __uint_as_float(h);
    asm("cvt.rna.tf32.f32 %0, %1;" : "=r"(l) : "f"(r));
    return make_uint2(h, l);
}

#define MMA(c, a, b0, b1)                                                      \
    asm volatile(                                                              \
        "mma.sync.aligned.m16n8k8.row.col.f32.tf32.tf32.f32 "                  \
        "{%0,%1,%2,%3}, {%4,%5,%6,%7}, {%8,%9}, {%0,%1,%2,%3};"                \
        : "+f"((c)[0]), "+f"((c)[1]), "+f"((c)[2]), "+f"((c)[3])               \
        : "r"((a)[0]), "r"((a)[1]), "r"((a)[2]), "r"((a)[3]),                  \
          "r"(b0), "r"(b1))

// ============================ GEMM: logits = x @ w^T ============================
// Grid 256: blockIdx = mblk*2 + nblk (adjacent CTAs share the A tile -> L2 reuse).
// 256 threads = 8 warps; warp tile 32(m) x 64(n); acc = Ah*Bh, err = the three
// small cross terms in a separate accumulator (partial sums ~2^-11 scale).
__global__ __launch_bounds__(256, 1)
void gate_gemm_kernel(const float* __restrict__ x, const float* __restrict__ w)
{
    extern __shared__ __align__(1024) float smem[];
    const int tid  = threadIdx.x;
    const int lane = tid & 31;
    const int wid  = tid >> 5;
    const int blockM = (blockIdx.x >> 1) * BM;
    const int blockN = (blockIdx.x & 1)  * BN;

    // ---- fill constants: thread covers row (tid>>1) of A AND of B, k-half (tid&1) ----
    const int frow   = tid >> 1;         // 0..127
    const int f_ks   = tid & 1;          // kstep within BK=16
    const int a_mt   = frow >> 4;        // m16 tile
    const int fg     = frow & 7;         // groupID
    const int a_half = (frow >> 3) & 1;  // a0/a1 vs a2/a3 row half
    const int b_nt   = frow >> 3;        // n8 tile

    const float* xp0 = x + (size_t)(blockM + frow) * DDIM + f_ks * 8;
    const float* wp0 = w + (size_t)(blockN + frow) * DDIM + f_ks * 8;

    float4 ga[2], gb[2];
    auto load_g = [&](int kt) {
        const float* xp = xp0 + kt * BK;
        const float* wp = wp0 + kt * BK;
        ga[0] = *reinterpret_cast<const float4*>(xp);
        ga[1] = *reinterpret_cast<const float4*>(xp + 4);
        gb[0] = *reinterpret_cast<const float4*>(wp);
        gb[1] = *reinterpret_cast<const float4*>(wp + 4);
    };

    // Fragment-order SMEM:
    // A block per (m16 tile, kstep): 256 floats; [lane]{a0h,a0l,a1h,a1l} then [lane]{a2h,a2l,a3h,a3l}
    // B block per (n8 tile, kstep): 128 floats; [lane]{b0h,b0l,b1h,b1l}
    auto fill = [&](int stg) {
        float* sa = smem + stg * STAGE;
        float* sb = sa + A_STAGE;
#pragma unroll
        for (int qq = 0; qq < 2; qq++) {           // k-quad within kstep
            float ea[4] = {ga[qq].x, ga[qq].y, ga[qq].z, ga[qq].w};
            float eb[4] = {gb[qq].x, gb[qq].y, gb[qq].z, gb[qq].w};
#pragma unroll
            for (int i = 0; i < 4; i++) {
                int offA = (a_mt * 2 + f_ks) * 256 + qq * 128
                         + (4 * fg + i) * 4 + a_half * 2;
                *reinterpret_cast<uint2*>(sa + offA) = split_tf32(ea[i]);
                int offB = ((b_nt * 2 + f_ks) * 32 + 4 * fg + i) * 4 + qq * 2;
                *reinterpret_cast<uint2*>(sb + offB) = split_tf32(eb[i]);
            }
        }
    };

    float acc[2][8][4], err[2][8][4];
#pragma unroll
    for (int mi = 0; mi < 2; mi++)
#pragma unroll
        for (int nj = 0; nj < 8; nj++)
#pragma unroll
            for (int c = 0; c < 4; c++) { acc[mi][nj][c] = 0.f; err[mi][nj][c] = 0.f; }

    const int wm = wid >> 1;    // 0..3: m32 slab
    const int wn = wid & 1;     // 0..1: n64 slab

    auto compute = [&](int stg) {
        const uint4* A4 = reinterpret_cast<const uint4*>(smem + stg * STAGE);
        const uint4* B4 = reinterpret_cast<const uint4*>(smem + stg * STAGE + A_STAGE);
#pragma unroll
        for (int ks = 0; ks < 2; ks++) {
            uint32_t ah[2][4], al[2][4];
#pragma unroll
            for (int mi = 0; mi < 2; mi++) {
                int b4 = ((wm * 2 + mi) * 2 + ks) * 64;
                uint4 p0 = A4[b4 + lane];
                uint4 p1 = A4[b4 + 32 + lane];
                ah[mi][0] = p0.x; al[mi][0] = p0.y;
                ah[mi][1] = p0.z; al[mi][1] = p0.w;
                ah[mi][2] = p1.x; al[mi][2] = p1.y;
                ah[mi][3] = p1.z; al[mi][3] = p1.w;
            }
#pragma unroll
            for (int nj = 0; nj < 8; nj++) {
                uint4 bb = B4[((wn * 8 + nj) * 2 + ks) * 32 + lane];
#pragma unroll
                for (int mi = 0; mi < 2; mi++) {
                    MMA(acc[mi][nj], ah[mi], bb.x, bb.z);   // Ah*Bh -> main
                    MMA(err[mi][nj], ah[mi], bb.y, bb.w);   // Ah*Bl -> err
                    MMA(err[mi][nj], al[mi], bb.x, bb.z);   // Al*Bh -> err
                    MMA(err[mi][nj], al[mi], bb.y, bb.w);   // Al*Bl -> err
                }
            }
        }
    };

    // ---- pipelined mainloop ----
    load_g(0);
    fill(0);
    __syncthreads();
    for (int kt = 0; kt < NKT; kt++) {
        if (kt + 1 < NKT) load_g(kt + 1);
        compute(kt & 1);
        if (kt + 1 < NKT) fill((kt + 1) & 1);
        __syncthreads();
    }

    // ---- write logits = acc + err ----
    const int g  = lane >> 2;
    const int t2 = (lane & 3) * 2;
#pragma unroll
    for (int mi = 0; mi < 2; mi++)
#pragma unroll
        for (int nj = 0; nj < 8; nj++) {
            int row = blockM + wm * 32 + mi * 16 + g;
            int col = blockN + wn * 64 + nj * 8 + t2;
            float* c = acc[mi][nj];
            float* e = err[mi][nj];
            *reinterpret_cast<float2*>(&g_logits[(size_t)row * NEXP + col]) =
                make_float2(c[0] + e[0], c[1] + e[1]);
            *reinterpret_cast<float2*>(&g_logits[(size_t)(row + 8) * NEXP + col]) =
                make_float2(c[2] + e[2], c[3] + e[3]);
        }
}

// ============================ routing (R1's proven epilogue) ============================
__global__ __launch_bounds__(256)
void route_kernel(const float* __restrict__ bias,
                  float* __restrict__ out_w,
                  float* __restrict__ out_i,
                  float* __restrict__ load)
{
    const int lane = threadIdx.x & 31;
    const int wid  = threadIdx.x >> 5;
    const int tok0 = (blockIdx.x * 8 + wid) * 16;

    float bia[8];
#pragma unroll
    for (int j = 0; j < 8; j++)
        bia[j] = bias[(j < 4) ? lane * 4 + j : 128 + lane * 4 + (j - 4)];

    for (int i = 0; i < 16; i++) {
        const int tok = tok0 + i;
        float v[8];
        *reinterpret_cast<float4*>(&v[0]) =
            *reinterpret_cast<const float4*>(&g_logits[(size_t)tok * NEXP + lane * 4]);
        *reinterpret_cast<float4*>(&v[4]) =
            *reinterpret_cast<const float4*>(&g_logits[(size_t)tok * NEXP + 128 + lane * 4]);

        // softmax over 256 logits (warp-wide)
        float mx = v[0];
#pragma unroll
        for (int j = 1; j < 8; j++) mx = fmaxf(mx, v[j]);
#pragma unroll
        for (int off = 16; off >= 1; off >>= 1)
            mx = fmaxf(mx, __shfl_xor_sync(0xffffffffu, mx, off));

        float s[8], sum = 0.f;
#pragma unroll
        for (int j = 0; j < 8; j++) { s[j] = expf(v[j] - mx); sum += s[j]; }
#pragma unroll
        for (int off = 16; off >= 1; off >>= 1)
            sum += __shfl_xor_sync(0xffffffffu, sum, off);
        float inv = 1.f / sum;

        float sel[8];
#pragma unroll
        for (int j = 0; j < 8; j++) { s[j] *= inv; sel[j] = s[j] + bia[j]; }

        // group scores: slots 0..3 -> group (lane>>3); 4..7 -> group 4+(lane>>3)
        float g0 = fmaxf(fmaxf(sel[0], sel[1]), fmaxf(sel[2], sel[3]));
        float g1 = fmaxf(fmaxf(sel[4], sel[5]), fmaxf(sel[6], sel[7]));
#pragma unroll
        for (int off = 1; off < 8; off <<= 1) {
            g0 = fmaxf(g0, __shfl_xor_sync(0xffffffffu, g0, off));
            g1 = fmaxf(g1, __shfl_xor_sync(0xffffffffu, g1, off));
        }
        float g[8];
#pragma unroll
        for (int q = 0; q < 4; q++) {
            g[q]     = __shfl_sync(0xffffffffu, g0, q * 8);
            g[4 + q] = __shfl_sync(0xffffffffu, g1, q * 8);
        }
        // top-4 groups (tie -> lower group index)
        unsigned kept = 0;
#pragma unroll
        for (int t = 0; t < 8; t++) {
            int rank = 0;
#pragma unroll
            for (int u = 0; u < 8; u++)
                rank += (g[u] > g[t]) || (g[u] == g[t] && u < t);
            if (rank < 4) kept |= (1u << t);
        }
        int myg = lane >> 3;
        if (!((kept >> myg) & 1u))       { sel[0] = sel[1] = sel[2] = sel[3] = -INFINITY; }
        if (!((kept >> (4 + myg)) & 1u)) { sel[4] = sel[5] = sel[6] = sel[7] = -INFINITY; }

        // iterative top-8 (descending; tie -> smaller expert index)
        float wsel = 0.f; int isel = 0;
#pragma unroll
        for (int kk = 0; kk < 8; kk++) {
            float bv = sel[0]; int bj = 0;
#pragma unroll
            for (int j = 1; j < 8; j++)
                if (sel[j] > bv) { bv = sel[j]; bj = j; }
            int   be = (bj < 4) ? lane * 4 + bj : 128 + lane * 4 + (bj - 4);
            float bs = s[bj];
#pragma unroll
            for (int off = 16; off >= 1; off >>= 1) {
                float ov = __shfl_xor_sync(0xffffffffu, bv, off);
                int   oe = __shfl_xor_sync(0xffffffffu, be, off);
                float os = __shfl_xor_sync(0xffffffffu, bs, off);
                if (ov > bv || (ov == bv && oe < be)) { bv = ov; be = oe; bs = os; }
            }
            if (lane == kk) { wsel = bs * 2.5f; isel = be; }
            int owner = (be & 127) >> 2;
            if (lane == owner) {
                int j = (be & 3) + ((be >= 128) ? 4 : 0);
                sel[j] = -INFINITY;
            }
        }

        if (lane < 8) {
            out_w[tok * TOPK + lane] = wsel;
            out_i[tok * TOPK + lane] = (float)isel;
            atomicAdd(&load[isel], 1.0f);
        }
    }
}

extern "C" void kernel_launch(void* const* d_in, const int* in_sizes, int n_in,
                              void* d_out, int out_size)
{
    const float* x    = (const float*)d_in[0];
    const float* w    = (const float*)d_in[1];
    const float* bias = (const float*)d_in[2];

    float* out   = (float*)d_out;
    float* out_w = out;
    float* out_i = out + (size_t)T_TOKENS * TOPK;
    float* load  = out + (size_t)2 * T_TOKENS * TOPK;

    static int attr_done = 0;
    if (!attr_done) {
        cudaFuncSetAttribute(gate_gemm_kernel,
                             cudaFuncAttributeMaxDynamicSharedMemorySize, SMEM_BYTES);
        attr_done = 1;
    }

    cudaMemsetAsync(load, 0, NEXP * sizeof(float), 0);
    gate_gemm_kernel<<<(T_TOKENS / BM) * (NEXP / BN), 256, SMEM_BYTES>>>(x, w);
    route_kernel<<<T_TOKENS / (8 * 16), 256>>>(bias, out_w, out_i, load);
}